// round 2
// baseline (speedup 1.0000x reference)
#include <cuda_runtime.h>
#include <cstdint>

// Problem constants
#define HH 64
#define WW 64
#define CC 3
#define KH 4
#define KW 4
#define NH 16
#define NW 16
#define NPATCH 768          // NH*NW*C
#define PDIM 16             // KH*KW
#define NCOMP 16
#define NBIN 200
#define NN 4096
#define DD 12288            // H*W*C
#define TT 12288            // NPATCH*NCOMP

#define ROWS_PER_BLOCK 512
#define ROW_BLOCKS (NN / ROWS_PER_BLOCK)   // 8
#define TILE_ROWS 16
#define TILES (ROWS_PER_BLOCK / TILE_ROWS) // 32

// partial log-jacobian per (patch, row): 768*4096 floats = 12.6 MB
__device__ float g_logj_partial[NPATCH * NN];

__global__ __launch_bounds__(256, 4)
void patch_transport_kernel(const float* __restrict__ data,
                            const float* __restrict__ wT,
                            const float* __restrict__ kx,
                            const float* __restrict__ ky,
                            const float* __restrict__ kd,
                            float* __restrict__ out)
{
    __shared__ float sx[NCOMP * NBIN];   // 12.8 KB
    __shared__ float sy[NCOMP * NBIN];
    __shared__ float sd[NCOMP * NBIN];
    __shared__ float sw[16 * 17];        // sw[k*17+c] = wT[p,k,c]
    __shared__ float spatch[16 * 17];
    __shared__ float sdelta[16 * 17];

    const int p   = blockIdx.x;          // patch 0..767
    const int tid = threadIdx.x;

    // ---- stage knots for this patch's 16 splines (contiguous in global) ----
    {
        const int tbase = p * NCOMP * NBIN;   // 3200 floats per table
        for (int i = tid; i < NCOMP * NBIN; i += 256) {
            sx[i] = kx[tbase + i];
            sy[i] = ky[tbase + i];
            sd[i] = kd[tbase + i];
        }
        int k = tid >> 4, c = tid & 15;
        sw[k * 17 + c] = wT[p * 256 + tid];
    }
    __syncthreads();

    const int r = tid >> 4;   // row within tile  0..15
    const int c = tid & 15;   // component / k index 0..15

    // patch -> (ph, pw, ch); element c -> (kh, kw)
    const int ph  = p / (NW * CC);
    const int rem = p % (NW * CC);
    const int pw  = rem / CC;
    const int ch  = rem % CC;
    const int base = ph * (KH * WW * CC) + pw * (KW * CC) + ch;   // ph*768 + pw*12 + ch
    const int offc = base + (c >> 2) * (WW * CC) + (c & 3) * CC;  // + kh*192 + kw*3

    const float* __restrict__ xxc = sx + c * NBIN;
    const float* __restrict__ yyc = sy + c * NBIN;
    const float* __restrict__ ddc = sd + c * NBIN;

    // endpoints (read after the staging sync)
    const float x0 = xxc[0], xl = xxc[NBIN - 1];
    const float y0 = yyc[0], yl = yyc[NBIN - 1];
    const float d0 = ddc[0], dl = ddc[NBIN - 1];

    const int rowbase = blockIdx.y * ROWS_PER_BLOCK;

    for (int tile = 0; tile < TILES; ++tile) {
        const int n = rowbase + tile * TILE_ROWS + r;

        // load patch element c of row (rowtile r)
        spatch[r * 17 + c] = data[(size_t)n * DD + offc];
        __syncthreads();

        // forward projection: X = sum_k patch[r][k] * wT[p,k,c]
        float X = 0.f;
        #pragma unroll
        for (int k = 0; k < 16; ++k)
            X = fmaf(spatch[r * 17 + k], sw[k * 17 + c], X);

        // ---- branchless binary search: lo = count(xx < X) ----
        int lo = 0;
        #pragma unroll
        for (int s = 128; s > 0; s >>= 1) {
            int m = lo + s;
            if (m <= NBIN && xxc[m - 1] < X) lo = m;
        }
        int k = min(max(lo - 1, 0), NBIN - 2);

        const float xk  = xxc[k], xk1 = xxc[k + 1];
        const float yk  = yyc[k], yk1 = yyc[k + 1];
        const float dk  = ddc[k], dk1 = ddc[k + 1];

        const float wx   = xk1 - xk;
        const float rwx  = __fdividef(1.f, wx);
        const float s_   = (yk1 - yk) * rwx;
        const float xi   = __saturatef((X - xk) * rwx);
        const float xi1  = 1.f - xi;
        const float xixi1 = xi * xi1;
        const float den  = fmaf(dk + dk1 - 2.f * s_, xixi1, s_);
        const float rden = __fdividef(1.f, den);
        const float num  = fmaf(s_ * xi, xi, dk * xixi1);
        float y    = fmaf(yk1 - yk, num * rden, yk);
        const float dnum = fmaf(dk1 * xi, xi, fmaf(2.f * s_, xixi1, dk * xi1 * xi1));
        float dydx = (s_ * s_) * dnum * (rden * rden);

        const bool below = X < x0;
        const bool above = X > xl;
        if (below) { y = fmaf(X - x0, d0, y0); dydx = d0; }
        else if (above) { y = fmaf(X - xl, dl, yl); dydx = dl; }

        float logd = __logf(dydx);
        sdelta[r * 17 + c] = y - X;

        // reduce logd over the 16 components of this row (lanes contiguous)
        #pragma unroll
        for (int ofs = 8; ofs > 0; ofs >>= 1)
            logd += __shfl_xor_sync(0xffffffffu, logd, ofs, 16);

        __syncthreads();

        // back-projection: this thread's c plays the role of k:
        // dpatch[k] = sum_cc delta[cc] * wT[p, k, cc]  ->  sw[c*17 + cc]
        float dp = 0.f;
        #pragma unroll
        for (int cc = 0; cc < 16; ++cc)
            dp = fmaf(sdelta[r * 17 + cc], sw[c * 17 + cc], dp);

        out[(size_t)n * DD + offc] = spatch[r * 17 + c] + dp;

        if (c == 0) g_logj_partial[p * NN + n] = logd;

        __syncthreads();   // protect spatch/sdelta before next tile
    }
}

__global__ __launch_bounds__(256)
void logj_reduce_kernel(float* __restrict__ out)
{
    const int n = blockIdx.x * 256 + threadIdx.x;
    float s0 = 0.f, s1 = 0.f, s2 = 0.f, s3 = 0.f;
    #pragma unroll 4
    for (int p = 0; p < NPATCH; p += 4) {
        s0 += g_logj_partial[(p + 0) * NN + n];
        s1 += g_logj_partial[(p + 1) * NN + n];
        s2 += g_logj_partial[(p + 2) * NN + n];
        s3 += g_logj_partial[(p + 3) * NN + n];
    }
    out[(size_t)NN * DD + n] = (s0 + s1) + (s2 + s3);
}

extern "C" void kernel_launch(void* const* d_in, const int* in_sizes, int n_in,
                              void* d_out, int out_size)
{
    const float* data = (const float*)d_in[0];
    const float* wT   = (const float*)d_in[1];
    const float* kx   = (const float*)d_in[2];
    const float* ky   = (const float*)d_in[3];
    const float* kd   = (const float*)d_in[4];
    float* out = (float*)d_out;

    dim3 grid(NPATCH, ROW_BLOCKS);
    patch_transport_kernel<<<grid, 256>>>(data, wT, kx, ky, kd, out);
    logj_reduce_kernel<<<NN / 256, 256>>>(out);
}

// round 3
// speedup vs baseline: 1.3650x; 1.3650x over previous
#include <cuda_runtime.h>
#include <cstdint>

// Problem constants
#define HH 64
#define WW 64
#define CC 3
#define KH 4
#define KW 4
#define NH 16
#define NW 16
#define NPATCH 768          // NH*NW*C
#define PDIM 16             // KH*KW
#define NCOMP 16
#define NBIN 200
#define NN 4096
#define DD 12288            // H*W*C
#define TT 12288            // NPATCH*NCOMP

#define ROWS_PER_BLOCK 512
#define ROW_BLOCKS (NN / ROWS_PER_BLOCK)   // 8
#define TILE_ROWS 16
#define TILES (ROWS_PER_BLOCK / TILE_ROWS) // 32

#define KSTRIDE 201          // padded knot row stride (9c mod 32 -> 16 distinct banks)
#define LUT_N 256
#define LUT_STRIDE 264       // bytes; 66 words == 2 mod 32 -> distinct banks across c
#define PSTRIDE 20           // padded patch/delta row stride (float4-aligned)

// scratch (device globals: no allocation allowed)
__device__ uint8_t g_lut[TT * LUT_N];                 // 3.1 MB
__device__ float   g_logj_partial[NPATCH * NN];       // 12.6 MB
__device__ float   g_logj_p2[8 * NN];                 // 128 KB

// ---------------------------------------------------------------------------
// LUT build: per spline, lut[i] = count(knots < x0 + i*(xl-x0)/LUT_N)
// ---------------------------------------------------------------------------
__global__ __launch_bounds__(256)
void build_lut_kernel(const float* __restrict__ kx)
{
    __shared__ float s[NCOMP * NBIN];
    const int p = blockIdx.x;
    const int tid = threadIdx.x;
    for (int i = tid; i < NCOMP * NBIN; i += 256) s[i] = kx[p * NCOMP * NBIN + i];
    __syncthreads();

    for (int e = tid; e < NCOMP * LUT_N; e += 256) {
        const int c = e >> 8;          // spline within patch
        const int i = e & (LUT_N - 1);
        const float* xx = s + c * NBIN;
        const float x0 = xx[0], xl = xx[NBIN - 1];
        const float gx = x0 + (xl - x0) * ((float)i * (1.0f / LUT_N));
        int lo = 0;
        #pragma unroll
        for (int st = 128; st > 0; st >>= 1) {
            int m = lo + st;
            if (m <= NBIN && xx[m - 1] < gx) lo = m;
        }
        g_lut[(p * NCOMP + c) * LUT_N + i] = (uint8_t)lo;
    }
}

// ---------------------------------------------------------------------------
// Main transport kernel
// ---------------------------------------------------------------------------
__global__ __launch_bounds__(256, 3)
void patch_transport_kernel(const float* __restrict__ data,
                            const float* __restrict__ wT,
                            const float* __restrict__ kx,
                            const float* __restrict__ ky,
                            const float* __restrict__ kd,
                            float* __restrict__ out)
{
    __shared__ float sx[NCOMP * KSTRIDE];      // 12.86 KB each
    __shared__ float sy[NCOMP * KSTRIDE];
    __shared__ float sd[NCOMP * KSTRIDE];
    __shared__ uint8_t slut[NCOMP * LUT_STRIDE]; // 4.2 KB
    __shared__ float sw[16 * 16];              // sw[k*16+c] = wT[p,k,c]
    __shared__ float spf[TILE_ROWS * PSTRIDE]; // patch tile (float4 rows)
    __shared__ float sdf[TILE_ROWS * PSTRIDE]; // delta tile

    const int p   = blockIdx.x;
    const int tid = threadIdx.x;

    // ---- stage knots (padded stride), w, LUT ----
    {
        const int tbase = p * NCOMP * NBIN;
        for (int i = tid; i < NCOMP * NBIN; i += 256) {
            const int c2 = i / NBIN, j = i - c2 * NBIN;
            const int di = c2 * KSTRIDE + j;
            sx[di] = kx[tbase + i];
            sy[di] = ky[tbase + i];
            sd[di] = kd[tbase + i];
        }
        sw[tid] = wT[p * 256 + tid];
        const uint32_t* gl32 = (const uint32_t*)(g_lut + (size_t)p * NCOMP * LUT_N);
        for (int e = tid; e < NCOMP * (LUT_N / 4); e += 256) {
            const int c2 = e >> 6, w = e & 63;
            *(uint32_t*)&slut[c2 * LUT_STRIDE + w * 4] = gl32[c2 * 64 + w];
        }
    }
    __syncthreads();

    const int r = tid >> 4;   // row within tile 0..15
    const int c = tid & 15;   // component / element index 0..15

    // w column c (forward) and row c (backward) into registers
    float4 wc0, wc1, wc2, wc3, wr0, wr1, wr2, wr3;
    wc0 = make_float4(sw[0*16+c], sw[1*16+c], sw[2*16+c], sw[3*16+c]);
    wc1 = make_float4(sw[4*16+c], sw[5*16+c], sw[6*16+c], sw[7*16+c]);
    wc2 = make_float4(sw[8*16+c], sw[9*16+c], sw[10*16+c], sw[11*16+c]);
    wc3 = make_float4(sw[12*16+c], sw[13*16+c], sw[14*16+c], sw[15*16+c]);
    wr0 = *(const float4*)&sw[c*16 + 0];
    wr1 = *(const float4*)&sw[c*16 + 4];
    wr2 = *(const float4*)&sw[c*16 + 8];
    wr3 = *(const float4*)&sw[c*16 + 12];

    // patch -> flat image offset for this thread's element
    const int ph  = p / (NW * CC);
    const int rem = p % (NW * CC);
    const int pw  = rem / CC;
    const int ch  = rem % CC;
    const int base = ph * (KH * WW * CC) + pw * (KW * CC) + ch;
    const int offc = base + (c >> 2) * (WW * CC) + (c & 3) * CC;

    const float* __restrict__ xxc = sx + c * KSTRIDE;
    const float* __restrict__ yyc = sy + c * KSTRIDE;
    const float* __restrict__ ddc = sd + c * KSTRIDE;
    const uint8_t* __restrict__ lutc = slut + c * LUT_STRIDE;

    const float x0 = xxc[0], xl = xxc[NBIN - 1];
    const float y0 = yyc[0], yl = yyc[NBIN - 1];
    const float d0 = ddc[0], dl = ddc[NBIN - 1];
    const float invstep = (float)LUT_N / (xl - x0);

    const int rowbase = blockIdx.y * ROWS_PER_BLOCK;

    for (int tile = 0; tile < TILES; ++tile) {
        const int n = rowbase + tile * TILE_ROWS + r;

        const float pv = data[(size_t)n * DD + offc];
        spf[r * PSTRIDE + c] = pv;
        __syncthreads();   // A

        // forward: X = patch_row . w_col(c)   (broadcast LDS.128 reads)
        const float4* rp = (const float4*)(spf + r * PSTRIDE);
        float4 a0 = rp[0], a1 = rp[1], a2 = rp[2], a3 = rp[3];
        float X = a0.x * wc0.x;
        X = fmaf(a0.y, wc0.y, X); X = fmaf(a0.z, wc0.z, X); X = fmaf(a0.w, wc0.w, X);
        X = fmaf(a1.x, wc1.x, X); X = fmaf(a1.y, wc1.y, X); X = fmaf(a1.z, wc1.z, X); X = fmaf(a1.w, wc1.w, X);
        X = fmaf(a2.x, wc2.x, X); X = fmaf(a2.y, wc2.y, X); X = fmaf(a2.z, wc2.z, X); X = fmaf(a2.w, wc2.w, X);
        X = fmaf(a3.x, wc3.x, X); X = fmaf(a3.y, wc3.y, X); X = fmaf(a3.z, wc3.z, X); X = fmaf(a3.w, wc3.w, X);

        // ---- LUT-accelerated searchsorted(left): lo = count(xx < X) ----
        int li = __float2int_rd((X - x0) * invstep);
        li = min(max(li, 0), LUT_N - 1);
        int lo = lutc[li];
        while (lo > 0 && xxc[lo - 1] >= X) --lo;     // guard fp rounding
        while (lo < NBIN && xxc[lo] < X) ++lo;       // advance within cell
        const int k = min(max(lo - 1, 0), NBIN - 2);

        const float xk  = xxc[k], xk1 = xxc[k + 1];
        const float yk  = yyc[k], yk1 = yyc[k + 1];
        const float dk  = ddc[k], dk1 = ddc[k + 1];

        const float wx   = xk1 - xk;
        const float rwx  = __fdividef(1.f, wx);
        const float s_   = (yk1 - yk) * rwx;
        const float xi   = __saturatef((X - xk) * rwx);
        const float xi1  = 1.f - xi;
        const float xixi1 = xi * xi1;
        const float den  = fmaf(dk + dk1 - 2.f * s_, xixi1, s_);
        const float rden = __fdividef(1.f, den);
        const float num  = fmaf(s_ * xi, xi, dk * xixi1);
        float y    = fmaf(yk1 - yk, num * rden, yk);
        const float dnum = fmaf(dk1 * xi, xi, fmaf(2.f * s_, xixi1, dk * xi1 * xi1));
        float dydx = (s_ * s_) * dnum * (rden * rden);

        const bool below = X < x0;
        const bool above = X > xl;
        if (below) { y = fmaf(X - x0, d0, y0); dydx = d0; }
        else if (above) { y = fmaf(X - xl, dl, yl); dydx = dl; }

        float logd = __logf(dydx);
        sdf[r * PSTRIDE + c] = y - X;

        // reduce logd over the 16 components of this row
        #pragma unroll
        for (int ofs = 8; ofs > 0; ofs >>= 1)
            logd += __shfl_xor_sync(0xffffffffu, logd, ofs, 16);

        __syncthreads();   // B

        // backward: dpatch[c] = delta_row . w_row(c)
        const float4* dq = (const float4*)(sdf + r * PSTRIDE);
        float4 b0 = dq[0], b1 = dq[1], b2 = dq[2], b3 = dq[3];
        float dp = b0.x * wr0.x;
        dp = fmaf(b0.y, wr0.y, dp); dp = fmaf(b0.z, wr0.z, dp); dp = fmaf(b0.w, wr0.w, dp);
        dp = fmaf(b1.x, wr1.x, dp); dp = fmaf(b1.y, wr1.y, dp); dp = fmaf(b1.z, wr1.z, dp); dp = fmaf(b1.w, wr1.w, dp);
        dp = fmaf(b2.x, wr2.x, dp); dp = fmaf(b2.y, wr2.y, dp); dp = fmaf(b2.z, wr2.z, dp); dp = fmaf(b2.w, wr2.w, dp);
        dp = fmaf(b3.x, wr3.x, dp); dp = fmaf(b3.y, wr3.y, dp); dp = fmaf(b3.z, wr3.z, dp); dp = fmaf(b3.w, wr3.w, dp);

        out[(size_t)n * DD + offc] = pv + dp;

        if (c == 0) g_logj_partial[p * NN + n] = logd;
        // next tile's spf store is ordered by sync A; sdf rewrite is after
        // next tile's sync A as well -> no trailing barrier needed
        __syncthreads();   // keeps spf stable until fwd reads complete next iter
    }
}

// ---------------------------------------------------------------------------
// log-Jacobian reduction, two stages for parallelism
// ---------------------------------------------------------------------------
__global__ __launch_bounds__(256)
void logj_reduce1(void)
{
    const int n  = blockIdx.x * 256 + threadIdx.x;
    const int p0 = blockIdx.y * (NPATCH / 8);      // 96 patches per y-block
    float s0 = 0.f, s1 = 0.f, s2 = 0.f, s3 = 0.f;
    #pragma unroll 4
    for (int p = p0; p < p0 + NPATCH / 8; p += 4) {
        s0 += g_logj_partial[(p + 0) * NN + n];
        s1 += g_logj_partial[(p + 1) * NN + n];
        s2 += g_logj_partial[(p + 2) * NN + n];
        s3 += g_logj_partial[(p + 3) * NN + n];
    }
    g_logj_p2[blockIdx.y * NN + n] = (s0 + s1) + (s2 + s3);
}

__global__ __launch_bounds__(256)
void logj_reduce2(float* __restrict__ out)
{
    const int n = blockIdx.x * 256 + threadIdx.x;
    float s = 0.f;
    #pragma unroll
    for (int g = 0; g < 8; ++g) s += g_logj_p2[g * NN + n];
    out[(size_t)NN * DD + n] = s;
}

extern "C" void kernel_launch(void* const* d_in, const int* in_sizes, int n_in,
                              void* d_out, int out_size)
{
    const float* data = (const float*)d_in[0];
    const float* wT   = (const float*)d_in[1];
    const float* kx   = (const float*)d_in[2];
    const float* ky   = (const float*)d_in[3];
    const float* kd   = (const float*)d_in[4];
    float* out = (float*)d_out;

    build_lut_kernel<<<NPATCH, 256>>>(kx);
    dim3 grid(NPATCH, ROW_BLOCKS);
    patch_transport_kernel<<<grid, 256>>>(data, wT, kx, ky, kd, out);
    logj_reduce1<<<dim3(NN / 256, 8), 256>>>();
    logj_reduce2<<<NN / 256, 256>>>(out);
}

// round 4
// speedup vs baseline: 1.6758x; 1.2277x over previous
#include <cuda_runtime.h>
#include <cstdint>

// Problem constants
#define HH 64
#define WW 64
#define CC 3
#define KH 4
#define KW 4
#define NH 16
#define NW 16
#define NPATCH 768          // NH*NW*C
#define PDIM 16             // KH*KW
#define NCOMP 16
#define NBIN 200
#define NN 4096
#define DD 12288            // H*W*C
#define TT 12288            // NPATCH*NCOMP

#define ROWS_PER_BLOCK 512
#define ROW_BLOCKS (NN / ROWS_PER_BLOCK)   // 8
#define ITERS (ROWS_PER_BLOCK / 16)        // 32 (16 rows per block per iteration)

#define KSTRIDE 201          // padded knot row stride (9c mod 32 -> distinct banks)
#define LUT_N 256
#define LUT_STRIDE 264       // bytes

// scratch (device globals: no allocation allowed)
__device__ uint8_t g_lut[TT * LUT_N];                 // 3.1 MB
__device__ float   g_logj_partial[NPATCH * NN];       // 12.6 MB
__device__ float   g_logj_p2[8 * NN];                 // 128 KB

// ---------------------------------------------------------------------------
// LUT build: per spline, lut[i] = count(knots < x0 + i*(xl-x0)/LUT_N)
// ---------------------------------------------------------------------------
__global__ __launch_bounds__(256)
void build_lut_kernel(const float* __restrict__ kx)
{
    __shared__ float s[NCOMP * NBIN];
    const int p = blockIdx.x;
    const int tid = threadIdx.x;
    for (int i = tid; i < NCOMP * NBIN; i += 256) s[i] = kx[p * NCOMP * NBIN + i];
    __syncthreads();

    for (int e = tid; e < NCOMP * LUT_N; e += 256) {
        const int c = e >> 8;
        const int i = e & (LUT_N - 1);
        const float* xx = s + c * NBIN;
        const float x0 = xx[0], xl = xx[NBIN - 1];
        const float gx = x0 + (xl - x0) * ((float)i * (1.0f / LUT_N));
        int lo = 0;
        #pragma unroll
        for (int st = 128; st > 0; st >>= 1) {
            int m = lo + st;
            if (m <= NBIN && xx[m - 1] < gx) lo = m;
        }
        g_lut[(p * NCOMP + c) * LUT_N + i] = (uint8_t)lo;
    }
}

// ---------------------------------------------------------------------------
// Main transport kernel — fully warp-synchronous tile loop (no barriers)
// ---------------------------------------------------------------------------
__global__ __launch_bounds__(256, 3)
void patch_transport_kernel(const float* __restrict__ data,
                            const float* __restrict__ wT,
                            const float* __restrict__ kx,
                            const float* __restrict__ ky,
                            const float* __restrict__ kd,
                            float* __restrict__ out)
{
    __shared__ float sx[NCOMP * KSTRIDE];        // 12.86 KB each
    __shared__ float sy[NCOMP * KSTRIDE];
    __shared__ float sd[NCOMP * KSTRIDE];
    __shared__ uint8_t slut[NCOMP * LUT_STRIDE]; // 4.2 KB
    __shared__ float sw[16 * 16];                // sw[k*16+c] = wT[p,k,c]

    const int p   = blockIdx.x;
    const int tid = threadIdx.x;

    // ---- stage knots (padded stride), w, LUT ----
    {
        const int tbase = p * NCOMP * NBIN;
        for (int i = tid; i < NCOMP * NBIN; i += 256) {
            const int c2 = i / NBIN, j = i - c2 * NBIN;
            const int di = c2 * KSTRIDE + j;
            sx[di] = kx[tbase + i];
            sy[di] = ky[tbase + i];
            sd[di] = kd[tbase + i];
        }
        sw[tid] = wT[p * 256 + tid];
        const uint32_t* gl32 = (const uint32_t*)(g_lut + (size_t)p * NCOMP * LUT_N);
        for (int e = tid; e < NCOMP * (LUT_N / 4); e += 256) {
            const int c2 = e >> 6, w = e & 63;
            *(uint32_t*)&slut[c2 * LUT_STRIDE + w * 4] = gl32[c2 * 64 + w];
        }
    }
    __syncthreads();   // the ONLY block barrier

    const int lane = tid & 31;
    const int wid  = tid >> 5;     // warp 0..7
    const int half = lane >> 4;    // row parity within warp
    const int c    = lane & 15;    // component / element index

    // w column c (forward) and row c (backward) into registers
    float wc[16], wr[16];
    #pragma unroll
    for (int k = 0; k < 16; ++k) wc[k] = sw[k * 16 + c];
    #pragma unroll
    for (int k = 0; k < 16; ++k) wr[k] = sw[c * 16 + k];

    // patch -> flat image offset for this thread's element
    const int ph  = p / (NW * CC);
    const int rem = p % (NW * CC);
    const int pw  = rem / CC;
    const int ch  = rem % CC;
    const int base = ph * (KH * WW * CC) + pw * (KW * CC) + ch;
    const int offc = base + (c >> 2) * (WW * CC) + (c & 3) * CC;

    const float* __restrict__ xxc = sx + c * KSTRIDE;
    const float* __restrict__ yyc = sy + c * KSTRIDE;
    const float* __restrict__ ddc = sd + c * KSTRIDE;
    const uint8_t* __restrict__ lutc = slut + c * LUT_STRIDE;

    const float x0 = xxc[0], xl = xxc[NBIN - 1];
    const float y0 = yyc[0], yl = yyc[NBIN - 1];
    const float d0 = ddc[0], dl = ddc[NBIN - 1];
    const float invstep = (float)LUT_N / (xl - x0);

    const int rowbase = blockIdx.y * ROWS_PER_BLOCK;
    const int rsub = wid * 2 + half;      // 0..15: this thread's row slot

    // software-pipelined scattered load
    int n = rowbase + rsub;
    float pv = data[(size_t)n * DD + offc];

    for (int it = 0; it < ITERS; ++it) {
        const int n_cur = n;
        const float pv_cur = pv;
        n += 16;
        if (it + 1 < ITERS) pv = data[(size_t)n * DD + offc];

        // forward: X = patch_row . w_col(c)  via width-16 shuffle broadcast
        float X = 0.f;
        #pragma unroll
        for (int k = 0; k < 16; ++k) {
            float pk = __shfl_sync(0xffffffffu, pv_cur, k, 16);
            X = fmaf(pk, wc[k], X);
        }

        // ---- LUT-accelerated searchsorted(left): lo = count(xx < X) ----
        int li = __float2int_rd((X - x0) * invstep);
        li = min(max(li, 0), LUT_N - 1);
        int lo = lutc[li];
        while (lo > 0 && xxc[lo - 1] >= X) --lo;     // fp-rounding guard
        while (lo < NBIN && xxc[lo] < X) ++lo;       // advance within cell
        const int k = min(max(lo - 1, 0), NBIN - 2);

        const float xk  = xxc[k], xk1 = xxc[k + 1];
        const float yk  = yyc[k], yk1 = yyc[k + 1];
        const float dk  = ddc[k], dk1 = ddc[k + 1];

        const float wx   = xk1 - xk;
        const float rwx  = __fdividef(1.f, wx);
        const float s_   = (yk1 - yk) * rwx;
        const float xi   = __saturatef((X - xk) * rwx);
        const float xi1  = 1.f - xi;
        const float xixi1 = xi * xi1;
        const float den  = fmaf(dk + dk1 - 2.f * s_, xixi1, s_);
        const float rden = __fdividef(1.f, den);
        const float num  = fmaf(s_ * xi, xi, dk * xixi1);
        float y    = fmaf(yk1 - yk, num * rden, yk);
        const float dnum = fmaf(dk1 * xi, xi, fmaf(2.f * s_, xixi1, dk * xi1 * xi1));
        float dydx = (s_ * s_) * dnum * (rden * rden);

        const bool below = X < x0;
        const bool above = X > xl;
        if (below) { y = fmaf(X - x0, d0, y0); dydx = d0; }
        else if (above) { y = fmaf(X - xl, dl, yl); dydx = dl; }

        float logd = __logf(dydx);
        const float delta = y - X;

        // reduce logd over the 16 lanes of this half-warp
        #pragma unroll
        for (int ofs = 8; ofs > 0; ofs >>= 1)
            logd += __shfl_xor_sync(0xffffffffu, logd, ofs, 16);

        // backward: dpatch[c] = delta_row . w_row(c)  via shuffle broadcast
        float dp = 0.f;
        #pragma unroll
        for (int cc = 0; cc < 16; ++cc) {
            float dcc = __shfl_sync(0xffffffffu, delta, cc, 16);
            dp = fmaf(dcc, wr[cc], dp);
        }

        out[(size_t)n_cur * DD + offc] = pv_cur + dp;
        if (c == 0) g_logj_partial[p * NN + n_cur] = logd;
    }
}

// ---------------------------------------------------------------------------
// log-Jacobian reduction, two stages
// ---------------------------------------------------------------------------
__global__ __launch_bounds__(256)
void logj_reduce1(void)
{
    const int n  = blockIdx.x * 256 + threadIdx.x;
    const int p0 = blockIdx.y * (NPATCH / 8);
    float s0 = 0.f, s1 = 0.f, s2 = 0.f, s3 = 0.f;
    #pragma unroll 4
    for (int p = p0; p < p0 + NPATCH / 8; p += 4) {
        s0 += g_logj_partial[(p + 0) * NN + n];
        s1 += g_logj_partial[(p + 1) * NN + n];
        s2 += g_logj_partial[(p + 2) * NN + n];
        s3 += g_logj_partial[(p + 3) * NN + n];
    }
    g_logj_p2[blockIdx.y * NN + n] = (s0 + s1) + (s2 + s3);
}

__global__ __launch_bounds__(256)
void logj_reduce2(float* __restrict__ out)
{
    const int n = blockIdx.x * 256 + threadIdx.x;
    float s = 0.f;
    #pragma unroll
    for (int g = 0; g < 8; ++g) s += g_logj_p2[g * NN + n];
    out[(size_t)NN * DD + n] = s;
}

extern "C" void kernel_launch(void* const* d_in, const int* in_sizes, int n_in,
                              void* d_out, int out_size)
{
    const float* data = (const float*)d_in[0];
    const float* wT   = (const float*)d_in[1];
    const float* kx   = (const float*)d_in[2];
    const float* ky   = (const float*)d_in[3];
    const float* kd   = (const float*)d_in[4];
    float* out = (float*)d_out;

    build_lut_kernel<<<NPATCH, 256>>>(kx);
    dim3 grid(NPATCH, ROW_BLOCKS);
    patch_transport_kernel<<<grid, 256>>>(data, wT, kx, ky, kd, out);
    logj_reduce1<<<dim3(NN / 256, 8), 256>>>();
    logj_reduce2<<<NN / 256, 256>>>(out);
}